// round 15
// baseline (speedup 1.0000x reference)
#include <cuda_runtime.h>
#include <cuda_fp16.h>
#include <cstdint>

#define N2    5120
#define NF    5121
#define NFP   5136
#define NFT   (NFP/2)      // 2568 frequency-pair blocks
#define LFULL 10240
#define BATCH 32
#define CIN   128
#define COUT  128
#define TSIG  8192
#define KW    2048
#define TOUT  8193

#define GTHR  640
#define PADR  5121

// per-ft block sizes (bytes)
#define WBLK  131072LL     // 128 o x 128 i x 2 f2 x 4
#define SBLK  32768LL      // 32 b x 128 i x 2 f2 x 4
#define CBLK  32768LL      // 32 b x 128 o x 2 f2 x 4

// ---------- scratch ----------
__device__ __align__(16) __half2 g_Ssp [BATCH*CIN*NFP];
__device__ __align__(16) __half2 g_Wsp [COUT*CIN*NFP];
__device__ __align__(16) __half2 g_Csp [BATCH*COUT*NFP];
__device__ float4 g_TWa[1705];
__device__ float2 g_TWb[1705];
__device__ uint16_t g_POS[NF];      // digit-reversal position table

__device__ __forceinline__ float2 cmul(float2 a, float2 b) {
    return make_float2(a.x*b.x - a.y*b.y, a.x*b.y + a.y*b.x);
}

__device__ __forceinline__ int pos_of_k(int k) {
    int p = (k & 3) * 1280; k >>= 2;
    p += (k & 3) * 320;     k >>= 2;
    p += (k & 3) * 80;      k >>= 2;
    p += (k & 3) * 20;      k >>= 2;
    p += (k & 3) * 5;       k >>= 2;
    return p + k;
}

#define BFLY4(x0,x1,x2,x3, wa, wb, o0,o1,o2,o3) do {                      \
    float2 s02 = make_float2(x0.x+x2.x, x0.y+x2.y);                        \
    float2 d02 = make_float2(x0.x-x2.x, x0.y-x2.y);                        \
    float2 s13 = make_float2(x1.x+x3.x, x1.y+x3.y);                        \
    float2 d13 = make_float2(x1.x-x3.x, x1.y-x3.y);                        \
    o0 = make_float2(s02.x+s13.x, s02.y+s13.y);                            \
    o1 = cmul(make_float2(d02.x+d13.y, d02.y-d13.x), make_float2(wa.x,wa.y)); \
    o2 = cmul(make_float2(s02.x-s13.x, s02.y-s13.y), make_float2(wa.z,wa.w)); \
    o3 = cmul(make_float2(d02.x-d13.y, d02.y+d13.x), wb);                  \
} while(0)

__device__ __forceinline__ void bfly5(float2* x) {
    const float c1 =  0.30901699437494745f, s1 = 0.9510565162951535f;
    const float c2 = -0.80901699437494734f, s2 = 0.5877852522924731f;
    float2 x0=x[0], x1=x[1], x2=x[2], x3=x[3], x4=x[4];
    float2 a1 = make_float2(x1.x + x4.x, x1.y + x4.y);
    float2 b1 = make_float2(x1.x - x4.x, x1.y - x4.y);
    float2 a2 = make_float2(x2.x + x3.x, x2.y + x3.y);
    float2 b2 = make_float2(x2.x - x3.x, x2.y - x3.y);
    x[0] = make_float2(x0.x + a1.x + a2.x, x0.y + a1.y + a2.y);
    float2 t1 = make_float2(x0.x + c1*a1.x + c2*a2.x, x0.y + c1*a1.y + c2*a2.y);
    float2 t2 = make_float2(x0.x + c2*a1.x + c1*a2.x, x0.y + c2*a1.y + c1*a2.y);
    float2 u1 = make_float2(s1*b1.x + s2*b2.x, s1*b1.y + s2*b2.y);
    float2 u2 = make_float2(s2*b1.x - s1*b2.x, s2*b1.y - s1*b2.y);
    x[1] = make_float2(t1.x + u1.y, t1.y - u1.x);
    x[2] = make_float2(t2.x + u2.y, t2.y - u2.x);
    x[3] = make_float2(t2.x - u2.y, t2.y + u2.x);
    x[4] = make_float2(t1.x - u1.y, t1.y + u1.x);
}

// ===== grouped (4-buffer) FFT stages, 640 threads =====
template<int S, int O1, int O2>
__device__ __forceinline__ void r16x4(float2 (*sm)[PADR]) {
    const int M2 = S / 16;
    #pragma unroll
    for (int g = threadIdx.x; g < 4*320; g += GTHR) {
        int c = g / 320;
        int q = g - c * 320;
        int sub = q / M2;
        int j2  = q - sub * M2;
        float2* s = sm[c];
        int base = sub * S + j2;
        float2 x[16];
        #pragma unroll
        for (int t = 0; t < 16; t++) x[t] = s[base + t*M2];
        #pragma unroll
        for (int u = 0; u < 4; u++) {
            float4 wa = g_TWa[O1 + u*M2 + j2];
            float2 wb = g_TWb[O1 + u*M2 + j2];
            BFLY4(x[u], x[u+4], x[u+8], x[u+12], wa, wb,
                  x[u], x[u+4], x[u+8], x[u+12]);
        }
        float4 wa2 = g_TWa[O2 + j2];
        float2 wb2 = g_TWb[O2 + j2];
        #pragma unroll
        for (int r = 0; r < 4; r++)
            BFLY4(x[4*r], x[4*r+1], x[4*r+2], x[4*r+3], wa2, wb2,
                  x[4*r], x[4*r+1], x[4*r+2], x[4*r+3]);
        #pragma unroll
        for (int t = 0; t < 16; t++) s[base + t*M2] = x[t];
    }
    __syncthreads();
}

__device__ __forceinline__ void r20x4(float2 (*sm)[PADR]) {
    #pragma unroll
    for (int g = threadIdx.x; g < 4*256; g += GTHR) {
        int c = g >> 8;
        int q = g & 255;
        float2* s = sm[c];
        int base = q * 20;
        float2 x[20];
        #pragma unroll
        for (int t = 0; t < 20; t++) x[t] = s[base + t];
        #pragma unroll
        for (int j2 = 0; j2 < 5; j2++) {
            float4 wa = g_TWa[1700 + j2];
            float2 wb = g_TWb[1700 + j2];
            BFLY4(x[j2], x[j2+5], x[j2+10], x[j2+15], wa, wb,
                  x[j2], x[j2+5], x[j2+10], x[j2+15]);
        }
        #pragma unroll
        for (int r = 0; r < 4; r++) bfly5(x + 5*r);
        #pragma unroll
        for (int t = 0; t < 20; t++) s[base + t] = x[t];
    }
    __syncthreads();
}

__device__ __forceinline__ void r5x4(float2 (*sm)[PADR]) {
    for (int g = threadIdx.x; g < 4*1024; g += GTHR) {
        int c = g >> 10;
        int q = g & 1023;
        float2* s = sm[c];
        float2 x[5];
        #pragma unroll
        for (int t = 0; t < 5; t++) x[t] = s[q*5 + t];
        bfly5(x);
        #pragma unroll
        for (int t = 0; t < 5; t++) s[q*5 + t] = x[t];
    }
    __syncthreads();
}

__device__ __forceinline__ float2 unpack_bin(const float2* s, int k) {
    int km = (k < N2) ? k : 0;
    int kn = (km == 0) ? 0 : N2 - km;
    float2 Zk = s[g_POS[km]];
    float2 Zn = s[g_POS[kn]];
    float2 A  = make_float2(Zk.x + Zn.x, Zk.y - Zn.y);
    float2 Bv = make_float2(Zk.x - Zn.x, Zk.y + Zn.y);
    float sn, cs;
    __sincosf(-6.2831853071795864769f * (float)k / (float)LFULL, &sn, &cs);
    float2 t = cmul(make_float2(cs, sn), Bv);
    return make_float2(0.5f*(A.x + t.y), 0.5f*(A.y - t.x));
}

// store bins (2t, 2t+1) for channel c at the ft-blocked layout
__device__ __forceinline__ void store_pair(char* base, long long boff, int t,
                                           long long blk, const float2* s) {
    float2 X0 = make_float2(0.f, 0.f), X1 = make_float2(0.f, 0.f);
    int k0 = 2*t;
    if (k0     < NF) X0 = unpack_bin(s, k0);
    if (k0 + 1 < NF) X1 = unpack_bin(s, k0 + 1);
    __half2 h0 = __floats2half2_rn(X0.x, X0.y);
    __half2 h1 = __floats2half2_rn(X1.x, X1.y);
    uint2 v;
    v.x = *(uint32_t*)&h0;
    v.y = *(uint32_t*)&h1;
    *(uint2*)(base + (long long)t*blk + boff) = v;
}

__global__ void init_tw() {
    int t = blockIdx.x * 256 + threadIdx.x;
    if (t < 1705) {
        int off, tw;
        if      (t < 1280) { off = 0;    tw = 1;   }
        else if (t < 1600) { off = 1280; tw = 4;   }
        else if (t < 1680) { off = 1600; tw = 16;  }
        else if (t < 1700) { off = 1680; tw = 64;  }
        else               { off = 1700; tw = 256; }
        int j = t - off;
        double a = -6.283185307179586476925286766559 * (double)(j * tw) / 5120.0;
        g_TWa[t] = make_float4((float)cos(a),   (float)sin(a),
                               (float)cos(2*a), (float)sin(2*a));
        g_TWb[t] = make_float2((float)cos(3*a), (float)sin(3*a));
    }
    if (t < NF) g_POS[t] = (uint16_t)pos_of_k(t < N2 ? t : 0);
}

// ---------- merged forward FFT: blocks [0,1024) = signal, [1024,5120) = weight ----------
__global__ __launch_bounds__(GTHR) void fft_fwd4(const float* __restrict__ sig,
                                                 const float* __restrict__ wgt) {
    extern __shared__ __align__(16) char smraw[];
    float2 (*sm)[PADR] = (float2 (*)[PADR])smraw;

    if (blockIdx.x < 1024) {
        int grp = blockIdx.x;            // b*32 + i4
        int b = grp >> 5, i4 = grp & 31;
        for (int c = 0; c < 4; c++) {
            const float* x = sig + (long long)(b*CIN + i4*4 + c) * TSIG;
            for (int n = threadIdx.x; n < N2; n += GTHR) {
                int a0 = 2*n     - 1024;
                int a1 = 2*n + 1 - 1024;
                float re = (a0 >= 0 && a0 < TSIG) ? x[a0] : 0.f;
                float im = (a1 >= 0 && a1 < TSIG) ? x[a1] : 0.f;
                sm[c][n] = make_float2(re, im);
            }
        }
        __syncthreads();
        r16x4<5120, 0, 1280>(sm);
        r16x4<320, 1600, 1680>(sm);
        r20x4(sm);

        char* base = (char*)g_Ssp;
        long long boff0 = (long long)b*1024 + i4*32;
        for (int u = threadIdx.x; u < 4*NFT; u += GTHR) {
            int c = u & 3, t = u >> 2;
            store_pair(base, boff0 + c*8, t, SBLK, sm[c]);
        }
    } else {
        int grp = blockIdx.x - 1024;     // o*32 + i4
        int o = grp >> 5, i4 = grp & 31;
        for (int c = 0; c < 4; c++) {
            const float* x = wgt + (long long)(o*CIN + i4*4 + c) * KW;
            for (int j = threadIdx.x; j < 1280; j += GTHR) {
                float2 x0 = make_float2(0.f, 0.f);
                if (j < 1024) x0 = make_float2(x[2*j], x[2*j + 1]);
                float4 wa = g_TWa[j];
                float2 w3 = g_TWb[j];
                sm[c][j]        = x0;
                sm[c][j + 1280] = cmul(x0, make_float2(wa.x, wa.y));
                sm[c][j + 2560] = cmul(x0, make_float2(wa.z, wa.w));
                sm[c][j + 3840] = cmul(x0, w3);
            }
        }
        __syncthreads();
        r16x4<1280, 1280, 1600>(sm);
        r16x4<80, 1680, 1700>(sm);
        r5x4(sm);

        char* base = (char*)g_Wsp;
        long long boff0 = (long long)o*1024 + i4*32;
        for (int u = threadIdx.x; u < 4*NFT; u += GTHR) {
            int c = u & 3, t = u >> 2;
            store_pair(base, boff0 + c*8, t, WBLK, sm[c]);
        }
    }
}

// ================= HMMA einsum: ft-blocked, LDS.32 fragments =================
__device__ __forceinline__ uint32_t smem_u32(const void* p) {
    uint32_t a;
    asm("{ .reg .u64 t; cvta.to.shared.u64 t, %1; cvt.u32.u64 %0, t; }" : "=r"(a) : "l"(p));
    return a;
}
__device__ __forceinline__ void cp16(uint32_t dst, const void* src) {
    asm volatile("cp.async.cg.shared.global [%0], [%1], 16;" :: "r"(dst), "l"(src));
}
__device__ __forceinline__ uint32_t lds32(uint32_t addr) {
    uint32_t v;
    asm volatile("ld.shared.b32 %0, [%1];" : "=r"(v) : "r"(addr));
    return v;
}
__device__ __forceinline__ uint32_t swadr(uint32_t base, int row, int i, int f) {
    return base + row*128 + ((((i >> 1) + row) & 7) << 4) + ((i & 1) << 3) + (f << 2);
}

#define STAGE_B  20480              // 16KB W + 4KB S
#define EIN_SMEM (4*STAGE_B)        // 80KB -> 2 CTA/SM

__global__ __launch_bounds__(256, 2) void einsum_mma() {
    extern __shared__ __align__(1024) char smem[];
    const uint32_t sbase = smem_u32(smem);
    const int tid  = threadIdx.x;
    const int lane = tid & 31;
    const int w    = tid >> 5;       // 8 warps
    const int fl   = w >> 2;         // f2 (0/1)
    const int m0   = (w & 3) * 32;   // o quarter
    const int ft   = blockIdx.x;
    const char* Wb = (const char*)g_Wsp + (long long)ft * WBLK;
    const char* Sb = (const char*)g_Ssp + (long long)ft * SBLK;

    auto fill = [&](int c) {
        uint32_t stg = sbase + (c & 3) * STAGE_B;
        #pragma unroll
        for (int it = 0; it < 4; it++) {
            int u = tid + it * 256;                 // 1024 W units
            int o = u >> 3, q = u & 7;
            cp16(stg + o*128 + (((q + o) & 7) << 4),
                 Wb + (long long)o*1024 + c*128 + q*16);
        }
        {
            int u = tid;                            // 256 S units
            int b = u >> 3, q = u & 7;
            cp16(stg + 16384 + b*128 + (((q + b) & 7) << 4),
                 Sb + (long long)b*1024 + c*128 + q*16);
        }
        asm volatile("cp.async.commit_group;" ::: "memory");
    };

    float acc[2][8][4];
    #pragma unroll
    for (int i = 0; i < 2; i++)
        #pragma unroll
        for (int j = 0; j < 8; j++)
            #pragma unroll
            for (int q = 0; q < 4; q++) acc[i][j][q] = 0.f;

    fill(0); fill(1); fill(2);

    for (int c = 0; c < 8; c++) {
        if (c < 6)       asm volatile("cp.async.wait_group 2;" ::: "memory");
        else if (c == 6) asm volatile("cp.async.wait_group 1;" ::: "memory");
        else             asm volatile("cp.async.wait_group 0;" ::: "memory");
        __syncthreads();
        if (c + 3 < 8) fill(c + 3);

        const uint32_t A = sbase + (c & 3) * STAGE_B;
        const uint32_t B = A + 16384;

        #pragma unroll
        for (int ks = 0; ks < 2; ks++) {
            int i0 = ks*8 + (lane & 3);
            uint32_t bfr[4][2], bfi[4][2];
            #pragma unroll
            for (int ni = 0; ni < 4; ni++) {
                int n = ni*8 + (lane >> 2);
                bfr[ni][0] = lds32(swadr(B, n, i0,     fl));
                bfr[ni][1] = lds32(swadr(B, n, i0 + 4, fl));
                bfi[ni][0] = __byte_perm(bfr[ni][0], 0, 0x1032) ^ 0x80000000u;
                bfi[ni][1] = __byte_perm(bfr[ni][1], 0, 0x1032) ^ 0x80000000u;
            }
            #pragma unroll
            for (int mi = 0; mi < 2; mi++) {
                int o = m0 + mi*16 + (lane >> 2);
                uint32_t a0 = lds32(swadr(A, o,     i0,     fl));
                uint32_t a1 = lds32(swadr(A, o + 8, i0,     fl));
                uint32_t a2 = lds32(swadr(A, o,     i0 + 4, fl));
                uint32_t a3 = lds32(swadr(A, o + 8, i0 + 4, fl));
                #pragma unroll
                for (int ni = 0; ni < 4; ni++) {
                    asm volatile(
                        "mma.sync.aligned.m16n8k16.row.col.f32.f16.f16.f32 "
                        "{%0,%1,%2,%3}, {%4,%5,%6,%7}, {%8,%9}, {%0,%1,%2,%3};"
                        : "+f"(acc[mi][ni][0]), "+f"(acc[mi][ni][1]),
                          "+f"(acc[mi][ni][2]), "+f"(acc[mi][ni][3])
                        : "r"(a0), "r"(a1), "r"(a2), "r"(a3),
                          "r"(bfr[ni][0]), "r"(bfr[ni][1]));
                    asm volatile(
                        "mma.sync.aligned.m16n8k16.row.col.f32.f16.f16.f32 "
                        "{%0,%1,%2,%3}, {%4,%5,%6,%7}, {%8,%9}, {%0,%1,%2,%3};"
                        : "+f"(acc[mi][ni+4][0]), "+f"(acc[mi][ni+4][1]),
                          "+f"(acc[mi][ni+4][2]), "+f"(acc[mi][ni+4][3])
                        : "r"(a0), "r"(a1), "r"(a2), "r"(a3),
                          "r"(bfi[ni][0]), "r"(bfi[ni][1]));
                }
            }
        }
    }
    __syncthreads();

    __half2* stg = (__half2*)smem;
    #pragma unroll
    for (int mi = 0; mi < 2; mi++)
        #pragma unroll
        for (int ni = 0; ni < 4; ni++)
            #pragma unroll
            for (int j = 0; j < 4; j++) {
                int b = ni*8 + (lane & 3)*2 + (j & 1);
                int o = m0 + mi*16 + (lane >> 2) + 8*(j >> 1);
                stg[(b*128 + o)*2 + fl] =
                    __floats2half2_rn(acc[mi][ni][j], acc[mi][ni + 4][j]);
            }
    __syncthreads();
    char* Cb = (char*)g_Csp + (long long)ft * CBLK;
    #pragma unroll
    for (int it = 0; it < 16; it++) {
        int u = tid + it * 256;          // 4096 8B units: [b][o]
        int b = u >> 7, o = u & 127;
        *(uint2*)(Cb + b*1024 + o*8) = *(const uint2*)&stg[u*2];
    }
}

// ---------- inverse real FFT: 4 output rows per CTA ----------
__global__ __launch_bounds__(GTHR) void ifft4_kernel(const float* __restrict__ bias,
                                                     float* __restrict__ out) {
    extern __shared__ __align__(16) char smraw[];
    float2 (*sm)[PADR] = (float2 (*)[PADR])smraw;
    int grp = blockIdx.x;            // b*32 + o4
    int b = grp >> 5, o4 = grp & 31;
    const char* Cb = (const char*)g_Csp;
    long long boff = (long long)b*1024 + o4*32;

    // phase 1: coalesced raw load of bins 0..5120 (fp16 -> fp32 into sm)
    for (int u = threadIdx.x; u < 4*2561; u += GTHR) {
        int c = u & 3, t = u >> 2;
        uint2 v = *(const uint2*)(Cb + (long long)t*CBLK + boff + c*8);
        __half2 h0 = *(__half2*)&v.x;
        __half2 h1 = *(__half2*)&v.y;
        sm[c][2*t] = __half22float2(h0);
        if (2*t + 1 <= N2) sm[c][2*t + 1] = __half22float2(h1);
    }
    __syncthreads();

    // phase 2: in-place repack pairs (k, N2-k)
    for (int u = threadIdx.x; u < 4*2561; u += GTHR) {
        int c = u & 3, k = u >> 2;       // 0..2560
        float2 Xk = sm[c][k];
        float2 Xn = sm[c][N2 - k];
        float sn, cs;
        __sincosf(6.2831853071795864769f * (float)k / (float)LFULL, &sn, &cs);
        float2 E  = make_float2(0.5f*(Xk.x + Xn.x), 0.5f*(Xk.y - Xn.y));
        float2 Ow = make_float2(0.5f*(Xk.x - Xn.x), 0.5f*(Xk.y + Xn.y));
        float2 O  = cmul(Ow, make_float2(cs, sn));
        float2 r0 = make_float2(E.x - O.y, -(E.y + O.x));
        float2 E2  = make_float2(0.5f*(Xn.x + Xk.x), 0.5f*(Xn.y - Xk.y));
        float2 Ow2 = make_float2(0.5f*(Xn.x - Xk.x), 0.5f*(Xn.y + Xk.y));
        float2 O2  = cmul(Ow2, make_float2(-cs, sn));
        float2 r1 = make_float2(E2.x - O2.y, -(E2.y + O2.x));
        sm[c][k] = r0;
        if (k != 0 && k != 2560) sm[c][N2 - k] = r1;
    }
    __syncthreads();

    r16x4<5120, 0, 1280>(sm);
    r16x4<320, 1600, 1680>(sm);
    r20x4(sm);

    const float inv = 1.0f / (float)N2;
    for (int c = 0; c < 4; c++) {
        int o = o4*4 + c;
        float bo = bias[o];
        float* op = out + (long long)(b*COUT + o) * TOUT;
        for (int n = threadIdx.x; n < 4097; n += GTHR) {
            float2 v = sm[c][g_POS[n]];
            op[2*n] = v.x * inv + bo;
            if (2*n + 1 < TOUT) op[2*n + 1] = -v.y * inv + bo;
        }
    }
}

// ---------- launch ----------
extern "C" void kernel_launch(void* const* d_in, const int* in_sizes, int n_in,
                              void* d_out, int out_size) {
    const float* sig  = (const float*)d_in[0];
    const float* wgt  = (const float*)d_in[1];
    const float* bias = (const float*)d_in[2];
    float* out = (float*)d_out;

    const int SMEM4 = 4 * PADR * sizeof(float2);   // 163,872 B

    cudaFuncSetAttribute(einsum_mma,  cudaFuncAttributeMaxDynamicSharedMemorySize, EIN_SMEM);
    cudaFuncSetAttribute(fft_fwd4,    cudaFuncAttributeMaxDynamicSharedMemorySize, SMEM4);
    cudaFuncSetAttribute(ifft4_kernel,cudaFuncAttributeMaxDynamicSharedMemorySize, SMEM4);

    init_tw<<<21, 256>>>();
    fft_fwd4<<<1024 + 4096, GTHR, SMEM4>>>(sig, wgt);
    einsum_mma<<<NFT, 256, EIN_SMEM>>>();
    ifft4_kernel<<<BATCH*COUT/4, GTHR, SMEM4>>>(bias, out);
    (void)in_sizes; (void)n_in; (void)out_size;
}

// round 16
// speedup vs baseline: 1.0491x; 1.0491x over previous
#include <cuda_runtime.h>
#include <cuda_fp16.h>
#include <cstdint>

#define N2    5120
#define NF    5121
#define NFP   5136
#define NFT   (NFP/2)      // 2568 frequency-pair blocks
#define LFULL 10240
#define BATCH 32
#define CIN   128
#define COUT  128
#define TSIG  8192
#define KW    2048
#define TOUT  8193

#define GTHR  640
#define PADR  5124         // even + 16B-aligned channel stride (5124*8 = 40992)

// per-ft block sizes (bytes)
#define WBLK  131072LL
#define SBLK  32768LL
#define CBLK  32768LL

// ---------- scratch ----------
__device__ __align__(16) __half2 g_Ssp [BATCH*CIN*NFP];
__device__ __align__(16) __half2 g_Wsp [COUT*CIN*NFP];
__device__ __align__(16) __half2 g_Csp [BATCH*COUT*NFP];
__device__ float4 g_TWa[1705];
__device__ float2 g_TWb[1705];
__device__ uint16_t g_POS[NF];

__device__ __forceinline__ float2 cmul(float2 a, float2 b) {
    return make_float2(a.x*b.x - a.y*b.y, a.x*b.y + a.y*b.x);
}

__device__ __forceinline__ int pos_of_k(int k) {
    int p = (k & 3) * 1280; k >>= 2;
    p += (k & 3) * 320;     k >>= 2;
    p += (k & 3) * 80;      k >>= 2;
    p += (k & 3) * 20;      k >>= 2;
    p += (k & 3) * 5;       k >>= 2;
    return p + k;
}

#define BFLY4(x0,x1,x2,x3, wa, wb, o0,o1,o2,o3) do {                      \
    float2 s02 = make_float2(x0.x+x2.x, x0.y+x2.y);                        \
    float2 d02 = make_float2(x0.x-x2.x, x0.y-x2.y);                        \
    float2 s13 = make_float2(x1.x+x3.x, x1.y+x3.y);                        \
    float2 d13 = make_float2(x1.x-x3.x, x1.y-x3.y);                        \
    o0 = make_float2(s02.x+s13.x, s02.y+s13.y);                            \
    o1 = cmul(make_float2(d02.x+d13.y, d02.y-d13.x), make_float2(wa.x,wa.y)); \
    o2 = cmul(make_float2(s02.x-s13.x, s02.y-s13.y), make_float2(wa.z,wa.w)); \
    o3 = cmul(make_float2(d02.x-d13.y, d02.y+d13.x), wb);                  \
} while(0)

__device__ __forceinline__ void bfly5(float2* x) {
    const float c1 =  0.30901699437494745f, s1 = 0.9510565162951535f;
    const float c2 = -0.80901699437494734f, s2 = 0.5877852522924731f;
    float2 x0=x[0], x1=x[1], x2=x[2], x3=x[3], x4=x[4];
    float2 a1 = make_float2(x1.x + x4.x, x1.y + x4.y);
    float2 b1 = make_float2(x1.x - x4.x, x1.y - x4.y);
    float2 a2 = make_float2(x2.x + x3.x, x2.y + x3.y);
    float2 b2 = make_float2(x2.x - x3.x, x2.y - x3.y);
    x[0] = make_float2(x0.x + a1.x + a2.x, x0.y + a1.y + a2.y);
    float2 t1 = make_float2(x0.x + c1*a1.x + c2*a2.x, x0.y + c1*a1.y + c2*a2.y);
    float2 t2 = make_float2(x0.x + c2*a1.x + c1*a2.x, x0.y + c2*a1.y + c1*a2.y);
    float2 u1 = make_float2(s1*b1.x + s2*b2.x, s1*b1.y + s2*b2.y);
    float2 u2 = make_float2(s2*b1.x - s1*b2.x, s2*b1.y - s1*b2.y);
    x[1] = make_float2(t1.x + u1.y, t1.y - u1.x);
    x[2] = make_float2(t2.x + u2.y, t2.y - u2.x);
    x[3] = make_float2(t2.x - u2.y, t2.y + u2.x);
    x[4] = make_float2(t1.x - u1.y, t1.y + u1.x);
}

// ===== grouped (4-buffer) FFT stages, 640 threads =====
template<int S, int O1, int O2>
__device__ __forceinline__ void r16x4(float2 (*sm)[PADR]) {
    const int M2 = S / 16;
    #pragma unroll
    for (int g = threadIdx.x; g < 4*320; g += GTHR) {
        int c = g / 320;
        int q = g - c * 320;
        int sub = q / M2;
        int j2  = q - sub * M2;
        float2* s = sm[c];
        int base = sub * S + j2;
        float2 x[16];
        #pragma unroll
        for (int t = 0; t < 16; t++) x[t] = s[base + t*M2];
        #pragma unroll
        for (int u = 0; u < 4; u++) {
            float4 wa = g_TWa[O1 + u*M2 + j2];
            float2 wb = g_TWb[O1 + u*M2 + j2];
            BFLY4(x[u], x[u+4], x[u+8], x[u+12], wa, wb,
                  x[u], x[u+4], x[u+8], x[u+12]);
        }
        float4 wa2 = g_TWa[O2 + j2];
        float2 wb2 = g_TWb[O2 + j2];
        #pragma unroll
        for (int r = 0; r < 4; r++)
            BFLY4(x[4*r], x[4*r+1], x[4*r+2], x[4*r+3], wa2, wb2,
                  x[4*r], x[4*r+1], x[4*r+2], x[4*r+3]);
        #pragma unroll
        for (int t = 0; t < 16; t++) s[base + t*M2] = x[t];
    }
    __syncthreads();
}

// radix-20 tail via float4 LDS.128 (conflict degree 8 -> 2)
__device__ __forceinline__ void r20x4(float2 (*sm)[PADR]) {
    #pragma unroll
    for (int g = threadIdx.x; g < 4*256; g += GTHR) {
        int c = g >> 8;
        int q = g & 255;
        float4* s4 = (float4*)(sm[c] + q*20);
        float2 x[20];
        #pragma unroll
        for (int t = 0; t < 10; t++) {
            float4 v = s4[t];
            x[2*t]     = make_float2(v.x, v.y);
            x[2*t + 1] = make_float2(v.z, v.w);
        }
        #pragma unroll
        for (int j2 = 0; j2 < 5; j2++) {
            float4 wa = g_TWa[1700 + j2];
            float2 wb = g_TWb[1700 + j2];
            BFLY4(x[j2], x[j2+5], x[j2+10], x[j2+15], wa, wb,
                  x[j2], x[j2+5], x[j2+10], x[j2+15]);
        }
        #pragma unroll
        for (int r = 0; r < 4; r++) bfly5(x + 5*r);
        #pragma unroll
        for (int t = 0; t < 10; t++)
            s4[t] = make_float4(x[2*t].x, x[2*t].y, x[2*t+1].x, x[2*t+1].y);
    }
    __syncthreads();
}

__device__ __forceinline__ void r5x4(float2 (*sm)[PADR]) {
    for (int g = threadIdx.x; g < 4*1024; g += GTHR) {
        int c = g >> 10;
        int q = g & 1023;
        float2* s = sm[c];
        float2 x[5];
        #pragma unroll
        for (int t = 0; t < 5; t++) x[t] = s[q*5 + t];
        bfly5(x);
        #pragma unroll
        for (int t = 0; t < 5; t++) s[q*5 + t] = x[t];
    }
    __syncthreads();
}

// unpack bin k given its twiddle w = e^{-2*pi*i*k/LFULL}
__device__ __forceinline__ float2 unpack_bin_w(const float2* s, int k, float2 w) {
    int km = (k < N2) ? k : 0;
    int kn = (km == 0) ? 0 : N2 - km;
    float2 Zk = s[g_POS[km]];
    float2 Zn = s[g_POS[kn]];
    float2 A  = make_float2(Zk.x + Zn.x, Zk.y - Zn.y);
    float2 Bv = make_float2(Zk.x - Zn.x, Zk.y + Zn.y);
    float2 t  = cmul(w, Bv);
    return make_float2(0.5f*(A.x + t.y), 0.5f*(A.y - t.x));
}

// store bins (2t, 2t+1): one sincos, odd twiddle derived by cmul step
__device__ __forceinline__ void store_pair(char* base, long long boff, int t,
                                           long long blk, const float2* s) {
    const float2 WSTEP = make_float2(0.99999981616429747f, -6.1359230376262155e-4f);
    int k0 = 2*t;
    float sn, cs;
    __sincosf(-6.2831853071795864769f * (float)k0 / (float)LFULL, &sn, &cs);
    float2 w0 = make_float2(cs, sn);
    float2 w1 = cmul(w0, WSTEP);
    float2 X0 = make_float2(0.f, 0.f), X1 = make_float2(0.f, 0.f);
    if (k0     < NF) X0 = unpack_bin_w(s, k0, w0);
    if (k0 + 1 < NF) X1 = unpack_bin_w(s, k0 + 1, w1);
    __half2 h0 = __floats2half2_rn(X0.x, X0.y);
    __half2 h1 = __floats2half2_rn(X1.x, X1.y);
    uint2 v;
    v.x = *(uint32_t*)&h0;
    v.y = *(uint32_t*)&h1;
    *(uint2*)(base + (long long)t*blk + boff) = v;
}

__global__ void init_tw() {
    int t = blockIdx.x * 256 + threadIdx.x;
    if (t < 1705) {
        int off, tw;
        if      (t < 1280) { off = 0;    tw = 1;   }
        else if (t < 1600) { off = 1280; tw = 4;   }
        else if (t < 1680) { off = 1600; tw = 16;  }
        else if (t < 1700) { off = 1680; tw = 64;  }
        else               { off = 1700; tw = 256; }
        int j = t - off;
        double a = -6.283185307179586476925286766559 * (double)(j * tw) / 5120.0;
        g_TWa[t] = make_float4((float)cos(a),   (float)sin(a),
                               (float)cos(2*a), (float)sin(2*a));
        g_TWb[t] = make_float2((float)cos(3*a), (float)sin(3*a));
    }
    if (t < NF) g_POS[t] = (uint16_t)pos_of_k(t < N2 ? t : 0);
}

// ---------- merged forward FFT: blocks [0,1024) = signal, [1024,5120) = weight ----------
__global__ __launch_bounds__(GTHR) void fft_fwd4(const float* __restrict__ sig,
                                                 const float* __restrict__ wgt) {
    extern __shared__ __align__(16) char smraw[];
    float2 (*sm)[PADR] = (float2 (*)[PADR])smraw;

    if (blockIdx.x < 1024) {
        int grp = blockIdx.x;            // b*32 + i4
        int b = grp >> 5, i4 = grp & 31;
        for (int c = 0; c < 4; c++) {
            const float* x = sig + (long long)(b*CIN + i4*4 + c) * TSIG;
            for (int n = threadIdx.x; n < N2; n += GTHR) {
                int a0 = 2*n     - 1024;
                int a1 = 2*n + 1 - 1024;
                float re = (a0 >= 0 && a0 < TSIG) ? x[a0] : 0.f;
                float im = (a1 >= 0 && a1 < TSIG) ? x[a1] : 0.f;
                sm[c][n] = make_float2(re, im);
            }
        }
        __syncthreads();
        r16x4<5120, 0, 1280>(sm);
        r16x4<320, 1600, 1680>(sm);
        r20x4(sm);

        char* base = (char*)g_Ssp;
        long long boff0 = (long long)b*1024 + i4*32;
        for (int u = threadIdx.x; u < 4*NFT; u += GTHR) {
            int c = u & 3, t = u >> 2;
            store_pair(base, boff0 + c*8, t, SBLK, sm[c]);
        }
    } else {
        int grp = blockIdx.x - 1024;     // o*32 + i4
        int o = grp >> 5, i4 = grp & 31;
        for (int c = 0; c < 4; c++) {
            const float* x = wgt + (long long)(o*CIN + i4*4 + c) * KW;
            for (int j = threadIdx.x; j < 1280; j += GTHR) {
                float2 x0 = make_float2(0.f, 0.f);
                if (j < 1024) x0 = make_float2(x[2*j], x[2*j + 1]);
                float4 wa = g_TWa[j];
                float2 w3 = g_TWb[j];
                sm[c][j]        = x0;
                sm[c][j + 1280] = cmul(x0, make_float2(wa.x, wa.y));
                sm[c][j + 2560] = cmul(x0, make_float2(wa.z, wa.w));
                sm[c][j + 3840] = cmul(x0, w3);
            }
        }
        __syncthreads();
        r16x4<1280, 1280, 1600>(sm);
        r16x4<80, 1680, 1700>(sm);
        r5x4(sm);

        char* base = (char*)g_Wsp;
        long long boff0 = (long long)o*1024 + i4*32;
        for (int u = threadIdx.x; u < 4*NFT; u += GTHR) {
            int c = u & 3, t = u >> 2;
            store_pair(base, boff0 + c*8, t, WBLK, sm[c]);
        }
    }
}

// ================= HMMA einsum: ft-blocked, LDS.32 fragments =================
__device__ __forceinline__ uint32_t smem_u32(const void* p) {
    uint32_t a;
    asm("{ .reg .u64 t; cvta.to.shared.u64 t, %1; cvt.u32.u64 %0, t; }" : "=r"(a) : "l"(p));
    return a;
}
__device__ __forceinline__ void cp16(uint32_t dst, const void* src) {
    asm volatile("cp.async.cg.shared.global [%0], [%1], 16;" :: "r"(dst), "l"(src));
}
__device__ __forceinline__ uint32_t lds32(uint32_t addr) {
    uint32_t v;
    asm volatile("ld.shared.b32 %0, [%1];" : "=r"(v) : "r"(addr));
    return v;
}
__device__ __forceinline__ uint32_t swadr(uint32_t base, int row, int i, int f) {
    return base + row*128 + ((((i >> 1) + row) & 7) << 4) + ((i & 1) << 3) + (f << 2);
}

#define STAGE_B  20480
#define EIN_SMEM (4*STAGE_B)

__global__ __launch_bounds__(256, 2) void einsum_mma() {
    extern __shared__ __align__(1024) char smem[];
    const uint32_t sbase = smem_u32(smem);
    const int tid  = threadIdx.x;
    const int lane = tid & 31;
    const int w    = tid >> 5;
    const int fl   = w >> 2;
    const int m0   = (w & 3) * 32;
    const int ft   = blockIdx.x;
    const char* Wb = (const char*)g_Wsp + (long long)ft * WBLK;
    const char* Sb = (const char*)g_Ssp + (long long)ft * SBLK;

    auto fill = [&](int c) {
        uint32_t stg = sbase + (c & 3) * STAGE_B;
        #pragma unroll
        for (int it = 0; it < 4; it++) {
            int u = tid + it * 256;
            int o = u >> 3, q = u & 7;
            cp16(stg + o*128 + (((q + o) & 7) << 4),
                 Wb + (long long)o*1024 + c*128 + q*16);
        }
        {
            int u = tid;
            int b = u >> 3, q = u & 7;
            cp16(stg + 16384 + b*128 + (((q + b) & 7) << 4),
                 Sb + (long long)b*1024 + c*128 + q*16);
        }
        asm volatile("cp.async.commit_group;" ::: "memory");
    };

    float acc[2][8][4];
    #pragma unroll
    for (int i = 0; i < 2; i++)
        #pragma unroll
        for (int j = 0; j < 8; j++)
            #pragma unroll
            for (int q = 0; q < 4; q++) acc[i][j][q] = 0.f;

    fill(0); fill(1); fill(2);

    for (int c = 0; c < 8; c++) {
        if (c < 6)       asm volatile("cp.async.wait_group 2;" ::: "memory");
        else if (c == 6) asm volatile("cp.async.wait_group 1;" ::: "memory");
        else             asm volatile("cp.async.wait_group 0;" ::: "memory");
        __syncthreads();
        if (c + 3 < 8) fill(c + 3);

        const uint32_t A = sbase + (c & 3) * STAGE_B;
        const uint32_t B = A + 16384;

        #pragma unroll
        for (int ks = 0; ks < 2; ks++) {
            int i0 = ks*8 + (lane & 3);
            uint32_t bfr[4][2], bfi[4][2];
            #pragma unroll
            for (int ni = 0; ni < 4; ni++) {
                int n = ni*8 + (lane >> 2);
                bfr[ni][0] = lds32(swadr(B, n, i0,     fl));
                bfr[ni][1] = lds32(swadr(B, n, i0 + 4, fl));
                bfi[ni][0] = __byte_perm(bfr[ni][0], 0, 0x1032) ^ 0x80000000u;
                bfi[ni][1] = __byte_perm(bfr[ni][1], 0, 0x1032) ^ 0x80000000u;
            }
            #pragma unroll
            for (int mi = 0; mi < 2; mi++) {
                int o = m0 + mi*16 + (lane >> 2);
                uint32_t a0 = lds32(swadr(A, o,     i0,     fl));
                uint32_t a1 = lds32(swadr(A, o + 8, i0,     fl));
                uint32_t a2 = lds32(swadr(A, o,     i0 + 4, fl));
                uint32_t a3 = lds32(swadr(A, o + 8, i0 + 4, fl));
                #pragma unroll
                for (int ni = 0; ni < 4; ni++) {
                    asm volatile(
                        "mma.sync.aligned.m16n8k16.row.col.f32.f16.f16.f32 "
                        "{%0,%1,%2,%3}, {%4,%5,%6,%7}, {%8,%9}, {%0,%1,%2,%3};"
                        : "+f"(acc[mi][ni][0]), "+f"(acc[mi][ni][1]),
                          "+f"(acc[mi][ni][2]), "+f"(acc[mi][ni][3])
                        : "r"(a0), "r"(a1), "r"(a2), "r"(a3),
                          "r"(bfr[ni][0]), "r"(bfr[ni][1]));
                    asm volatile(
                        "mma.sync.aligned.m16n8k16.row.col.f32.f16.f16.f32 "
                        "{%0,%1,%2,%3}, {%4,%5,%6,%7}, {%8,%9}, {%0,%1,%2,%3};"
                        : "+f"(acc[mi][ni+4][0]), "+f"(acc[mi][ni+4][1]),
                          "+f"(acc[mi][ni+4][2]), "+f"(acc[mi][ni+4][3])
                        : "r"(a0), "r"(a1), "r"(a2), "r"(a3),
                          "r"(bfi[ni][0]), "r"(bfi[ni][1]));
                }
            }
        }
    }
    __syncthreads();

    __half2* stg = (__half2*)smem;
    #pragma unroll
    for (int mi = 0; mi < 2; mi++)
        #pragma unroll
        for (int ni = 0; ni < 4; ni++)
            #pragma unroll
            for (int j = 0; j < 4; j++) {
                int b = ni*8 + (lane & 3)*2 + (j & 1);
                int o = m0 + mi*16 + (lane >> 2) + 8*(j >> 1);
                stg[(b*128 + o)*2 + fl] =
                    __floats2half2_rn(acc[mi][ni][j], acc[mi][ni + 4][j]);
            }
    __syncthreads();
    char* Cb = (char*)g_Csp + (long long)ft * CBLK;
    #pragma unroll
    for (int it = 0; it < 16; it++) {
        int u = tid + it * 256;
        int b = u >> 7, o = u & 127;
        *(uint2*)(Cb + b*1024 + o*8) = *(const uint2*)&stg[u*2];
    }
}

// ---------- inverse real FFT: 4 output rows per CTA ----------
__global__ __launch_bounds__(GTHR) void ifft4_kernel(const float* __restrict__ bias,
                                                     float* __restrict__ out) {
    extern __shared__ __align__(16) char smraw[];
    float2 (*sm)[PADR] = (float2 (*)[PADR])smraw;
    int grp = blockIdx.x;            // b*32 + o4
    int b = grp >> 5, o4 = grp & 31;
    const char* Cb = (const char*)g_Csp;
    long long boff = (long long)b*1024 + o4*32;

    // phase 1: coalesced raw load of bins 0..5120
    for (int u = threadIdx.x; u < 4*2561; u += GTHR) {
        int c = u & 3, t = u >> 2;
        uint2 v = *(const uint2*)(Cb + (long long)t*CBLK + boff + c*8);
        __half2 h0 = *(__half2*)&v.x;
        __half2 h1 = *(__half2*)&v.y;
        sm[c][2*t] = __half22float2(h0);
        if (2*t + 1 <= N2) sm[c][2*t + 1] = __half22float2(h1);
    }
    __syncthreads();

    // phase 2: in-place repack pairs (k, N2-k)
    for (int u = threadIdx.x; u < 4*2561; u += GTHR) {
        int c = u & 3, k = u >> 2;
        float2 Xk = sm[c][k];
        float2 Xn = sm[c][N2 - k];
        float sn, cs;
        __sincosf(6.2831853071795864769f * (float)k / (float)LFULL, &sn, &cs);
        float2 E  = make_float2(0.5f*(Xk.x + Xn.x), 0.5f*(Xk.y - Xn.y));
        float2 Ow = make_float2(0.5f*(Xk.x - Xn.x), 0.5f*(Xk.y + Xn.y));
        float2 O  = cmul(Ow, make_float2(cs, sn));
        float2 r0 = make_float2(E.x - O.y, -(E.y + O.x));
        float2 E2  = make_float2(0.5f*(Xn.x + Xk.x), 0.5f*(Xn.y - Xk.y));
        float2 Ow2 = make_float2(0.5f*(Xn.x - Xk.x), 0.5f*(Xn.y + Xk.y));
        float2 O2  = cmul(Ow2, make_float2(-cs, sn));
        float2 r1 = make_float2(E2.x - O2.y, -(E2.y + O2.x));
        sm[c][k] = r0;
        if (k != 0 && k != 2560) sm[c][N2 - k] = r1;
    }
    __syncthreads();

    r16x4<5120, 0, 1280>(sm);
    r16x4<320, 1600, 1680>(sm);
    r20x4(sm);

    const float inv = 1.0f / (float)N2;
    for (int c = 0; c < 4; c++) {
        int o = o4*4 + c;
        float bo = bias[o];
        float* op = out + (long long)(b*COUT + o) * TOUT;
        for (int n = threadIdx.x; n < 4097; n += GTHR) {
            float2 v = sm[c][g_POS[n]];
            op[2*n] = v.x * inv + bo;
            if (2*n + 1 < TOUT) op[2*n + 1] = -v.y * inv + bo;
        }
    }
}

// ---------- launch ----------
extern "C" void kernel_launch(void* const* d_in, const int* in_sizes, int n_in,
                              void* d_out, int out_size) {
    const float* sig  = (const float*)d_in[0];
    const float* wgt  = (const float*)d_in[1];
    const float* bias = (const float*)d_in[2];
    float* out = (float*)d_out;

    const int SMEM4 = 4 * PADR * sizeof(float2);   // 163,968 B

    cudaFuncSetAttribute(einsum_mma,  cudaFuncAttributeMaxDynamicSharedMemorySize, EIN_SMEM);
    cudaFuncSetAttribute(fft_fwd4,    cudaFuncAttributeMaxDynamicSharedMemorySize, SMEM4);
    cudaFuncSetAttribute(ifft4_kernel,cudaFuncAttributeMaxDynamicSharedMemorySize, SMEM4);

    init_tw<<<21, 256>>>();
    fft_fwd4<<<1024 + 4096, GTHR, SMEM4>>>(sig, wgt);
    einsum_mma<<<NFT, 256, EIN_SMEM>>>();
    ifft4_kernel<<<BATCH*COUT/4, GTHR, SMEM4>>>(bias, out);
    (void)in_sizes; (void)n_in; (void)out_size;
}